// round 4
// baseline (speedup 1.0000x reference)
#include <cuda_runtime.h>
#include <cuda_fp16.h>
#include <cstdint>

#define BATCH 16
#define SEQ   2048
#define DIM   128
#define TQ    128
#define TK    64
#define NTILE (SEQ/TK)
#define THREADS 640
#define NCONS 512          // 16 consumer warps
#define NPROD 128          // 4 producer warps
#define SCALE 0.08838834764831845f

// smem strides (elements)
#define QS  136
#define KS  136
#define VHS 136   // 272B rows: ldmatrix 16B-aligned, conflict-free
#define PSS 68

// smem layout (bytes)
#define OFF_Q  0
#define SZ_Q   (TQ*QS*2)                 // 34816
#define OFF_K  (OFF_Q + SZ_Q)
#define SZ_KB  (TK*KS*2)                 // 17408 per buffer
#define OFF_V  (OFF_K + 2*SZ_KB)
#define SZ_VB  (TK*VHS*2)                // 17408 per buffer
#define OFF_P  (OFF_V + 2*SZ_VB)
#define SZ_PB  (TQ*PSS*4)                // 34816 per buffer (double)
#define OFF_R  (OFF_P + 2*SZ_PB)
#define SMEM_BYTES (OFF_R + 512)         // 174592

// named barriers
#define B_KVFULL(p) (1+(p))
#define B_KVFREE(p) (3+(p))
#define B_PSFULL(p) (5+(p))
#define B_PSFREE(p) (7+(p))
#define B_CONS      9

__device__ __forceinline__ void bar_sync(int id, int cnt) {
    asm volatile("bar.sync %0, %1;" :: "r"(id), "r"(cnt) : "memory");
}
__device__ __forceinline__ void bar_arrive(int id, int cnt) {
    asm volatile("bar.arrive %0, %1;" :: "r"(id), "r"(cnt) : "memory");
}

__device__ __forceinline__ void mma16816(float* c,
    uint32_t a0, uint32_t a1, uint32_t a2, uint32_t a3,
    uint32_t b0, uint32_t b1)
{
    asm volatile(
        "mma.sync.aligned.m16n8k16.row.col.f32.f16.f16.f32 "
        "{%0,%1,%2,%3}, {%4,%5,%6,%7}, {%8,%9}, {%0,%1,%2,%3};\n"
        : "+f"(c[0]), "+f"(c[1]), "+f"(c[2]), "+f"(c[3])
        : "r"(a0), "r"(a1), "r"(a2), "r"(a3), "r"(b0), "r"(b1));
}

__device__ __forceinline__ void ldmx2t(uint32_t& b0, uint32_t& b1, const __half* p) {
    uint32_t s = (uint32_t)__cvta_generic_to_shared(p);
    asm volatile("ldmatrix.sync.aligned.m8n8.x2.trans.shared.b16 {%0,%1}, [%2];"
        : "=r"(b0), "=r"(b1) : "r"(s));
}

__device__ __forceinline__ uint32_t pack_f2(float x, float y) {
    __half2 h = __floats2half2_rn(x, y);
    return *reinterpret_cast<uint32_t*>(&h);
}

// producer: load TK x DIM fp32 tile -> fp16 smem buffer (stride rs halfs). 128 threads.
__device__ __forceinline__ void load_tile(const float* __restrict__ g, __half* dst, int rs, int pid) {
    #pragma unroll
    for (int j = 0; j < 16; ++j) {
        int i = pid + j * NPROD;            // 0..2047 float4 chunks
        float4 f = *(const float4*)(g + i * 4);
        int r = i >> 5, c4 = (i & 31) << 2;
        __half2 h0 = __floats2half2_rn(f.x, f.y);
        __half2 h1 = __floats2half2_rn(f.z, f.w);
        uint2 u; u.x = *(uint32_t*)&h0; u.y = *(uint32_t*)&h1;
        *(uint2*)(dst + r * rs + c4) = u;
    }
}

__global__ __launch_bounds__(THREADS, 1)
void attn_kernel(const float* __restrict__ q, const float* __restrict__ k,
                 const float* __restrict__ v, float* __restrict__ ctx,
                 float* __restrict__ attn)
{
    extern __shared__ char smem[];
    __half* Qh  = reinterpret_cast<__half*>(smem + OFF_Q);
    __half* Kb  = reinterpret_cast<__half*>(smem + OFF_K);
    __half* Vb  = reinterpret_cast<__half*>(smem + OFF_V);
    float*  Psb = reinterpret_cast<float*>(smem + OFF_P);
    float*  RI  = reinterpret_cast<float*>(smem + OFF_R);

    const int b    = blockIdx.y;
    const int q0   = blockIdx.x * TQ;
    const int tid  = threadIdx.x;

    const float* kbatch = k + ((size_t)b * SEQ) * DIM;
    const float* vbatch = v + ((size_t)b * SEQ) * DIM;

    // ---- Q tile load+convert (all threads) ----
    if (tid < TQ) RI[tid] = 0.f;
    {
        const float* qbase = q + ((size_t)(b * SEQ + q0)) * DIM;
        for (int i = tid; i < TQ * (DIM / 4); i += THREADS) {
            int r = i >> 5, c4 = (i & 31) << 2;
            float4 f = *(const float4*)(qbase + r * DIM + c4);
            __half2 h0 = __floats2half2_rn(f.x, f.y);
            __half2 h1 = __floats2half2_rn(f.z, f.w);
            uint2 u; u.x = *(uint32_t*)&h0; u.y = *(uint32_t*)&h1;
            *(uint2*)(Qh + r * QS + c4) = u;
        }
    }
    __syncthreads();

    if (tid >= NCONS) {
        // ========================= PRODUCER =========================
        const int pid = tid - NCONS;
        float* attnbase = attn + ((size_t)(b * SEQ + q0)) * SEQ;

        // ---- sweep 1: K only ----
        load_tile(kbatch, Kb, KS, pid);
        bar_arrive(B_KVFULL(0), THREADS);
        load_tile(kbatch + (size_t)TK * DIM, Kb + SZ_KB / 2, KS, pid);
        bar_arrive(B_KVFULL(1), THREADS);
        for (int kt = 0; kt + 2 < NTILE; ++kt) {
            bar_sync(B_KVFREE(kt & 1), THREADS);
            load_tile(kbatch + (size_t)(kt + 2) * TK * DIM, Kb + (kt & 1) * (SZ_KB / 2), KS, pid);
            bar_arrive(B_KVFULL(kt & 1), THREADS);
        }

        // ---- sweep 2 prologue: tiles 0,1 (K+V) ----
        bar_sync(B_KVFREE(0), THREADS);
        load_tile(kbatch, Kb, KS, pid);
        load_tile(vbatch, Vb, VHS, pid);
        bar_arrive(B_KVFULL(0), THREADS);
        bar_sync(B_KVFREE(1), THREADS);
        load_tile(kbatch + (size_t)TK * DIM, Kb + SZ_KB / 2, KS, pid);
        load_tile(vbatch + (size_t)TK * DIM, Vb + SZ_VB / 2, VHS, pid);
        bar_arrive(B_KVFULL(1), THREADS);

        for (int kt = 0; kt < NTILE; ++kt) {
            const int p = kt & 1;
            // attention write for tile kt from Ps[p]
            bar_sync(B_PSFULL(p), THREADS);
            {
                const float* src = Psb + p * (SZ_PB / 4);
                float* dst = attnbase + kt * TK;
                const int rr = pid >> 4, cc = (pid & 15) << 2;
                #pragma unroll
                for (int pp = 0; pp < 16; ++pp) {
                    int r = pp * 8 + rr;
                    float4 f = *(const float4*)(src + r * PSS + cc);
                    __stcs((float4*)(dst + (size_t)r * SEQ + cc), f);
                }
            }
            bar_arrive(B_PSFREE(p), THREADS);
            // load tile kt+2
            if (kt + 2 < NTILE) {
                bar_sync(B_KVFREE(p), THREADS);
                load_tile(kbatch + (size_t)(kt + 2) * TK * DIM, Kb + p * (SZ_KB / 2), KS, pid);
                load_tile(vbatch + (size_t)(kt + 2) * TK * DIM, Vb + p * (SZ_VB / 2), VHS, pid);
                bar_arrive(B_KVFULL(p), THREADS);
            }
        }
    } else {
        // ========================= CONSUMER =========================
        const int w    = tid >> 5;
        const int lane = tid & 31;
        const int g    = lane >> 2;
        const int t    = lane & 3;
        const int lr   = lane & 15;

        const int m0 = (w >> 1) * 16;   // QK rows
        const int nh = (w & 1);         // QK col half

        // ---- sweep 1: row sums ----
        float rs0 = 0.f, rs1 = 0.f;
        for (int kt = 0; kt < NTILE; ++kt) {
            const int p = kt & 1;
            bar_sync(B_KVFULL(p), THREADS);
            const __half* Kc = Kb + p * (SZ_KB / 2);

            float acc[4][4];
            #pragma unroll
            for (int j = 0; j < 4; ++j) { acc[j][0]=acc[j][1]=acc[j][2]=acc[j][3]=0.f; }
            #pragma unroll
            for (int kb2 = 0; kb2 < 8; ++kb2) {
                const int c0 = kb2 * 16 + t * 2;
                uint32_t a0 = *(const uint32_t*)(Qh + (m0 + g    ) * QS + c0);
                uint32_t a1 = *(const uint32_t*)(Qh + (m0 + g + 8) * QS + c0);
                uint32_t a2 = *(const uint32_t*)(Qh + (m0 + g    ) * QS + c0 + 8);
                uint32_t a3 = *(const uint32_t*)(Qh + (m0 + g + 8) * QS + c0 + 8);
                #pragma unroll
                for (int j = 0; j < 4; ++j) {
                    const int n = (nh * 4 + j) * 8 + g;
                    uint32_t b0 = *(const uint32_t*)(Kc + n * KS + c0);
                    uint32_t b1 = *(const uint32_t*)(Kc + n * KS + c0 + 8);
                    mma16816(acc[j], a0, a1, a2, a3, b0, b1);
                }
            }
            bar_arrive(B_KVFREE(p), THREADS);
            #pragma unroll
            for (int j = 0; j < 4; ++j) {
                rs0 += __expf(acc[j][0] * SCALE) + __expf(acc[j][1] * SCALE);
                rs1 += __expf(acc[j][2] * SCALE) + __expf(acc[j][3] * SCALE);
            }
        }
        rs0 += __shfl_xor_sync(0xffffffffu, rs0, 1);
        rs0 += __shfl_xor_sync(0xffffffffu, rs0, 2);
        rs1 += __shfl_xor_sync(0xffffffffu, rs1, 1);
        rs1 += __shfl_xor_sync(0xffffffffu, rs1, 2);
        if (t == 0) {
            atomicAdd(&RI[m0 + g], rs0);
            atomicAdd(&RI[m0 + g + 8], rs1);
        }
        bar_sync(B_CONS, NCONS);
        if (tid < TQ) RI[tid] = 1.f / RI[tid];
        bar_sync(B_CONS, NCONS);
        const float inv0 = RI[m0 + g];
        const float inv1 = RI[m0 + g + 8];

        // ---- sweep 2 ----
        const int mw  = (w & 7) * 16;   // PV rows
        const int nwc = (w >> 3) * 64;  // PV cols
        float cacc[8][4];
        #pragma unroll
        for (int nb = 0; nb < 8; ++nb) { cacc[nb][0]=cacc[nb][1]=cacc[nb][2]=cacc[nb][3]=0.f; }

        for (int kt = 0; kt < NTILE; ++kt) {
            const int p = kt & 1;
            bar_sync(B_KVFULL(p), THREADS);
            const __half* Kc = Kb + p * (SZ_KB / 2);
            const __half* Vc = Vb + p * (SZ_VB / 2);
            float* Psp = Psb + p * (SZ_PB / 4);

            // QK recompute (identical sequence to sweep 1)
            float acc[4][4];
            #pragma unroll
            for (int j = 0; j < 4; ++j) { acc[j][0]=acc[j][1]=acc[j][2]=acc[j][3]=0.f; }
            #pragma unroll
            for (int kb2 = 0; kb2 < 8; ++kb2) {
                const int c0 = kb2 * 16 + t * 2;
                uint32_t a0 = *(const uint32_t*)(Qh + (m0 + g    ) * QS + c0);
                uint32_t a1 = *(const uint32_t*)(Qh + (m0 + g + 8) * QS + c0);
                uint32_t a2 = *(const uint32_t*)(Qh + (m0 + g    ) * QS + c0 + 8);
                uint32_t a3 = *(const uint32_t*)(Qh + (m0 + g + 8) * QS + c0 + 8);
                #pragma unroll
                for (int j = 0; j < 4; ++j) {
                    const int n = (nh * 4 + j) * 8 + g;
                    uint32_t b0 = *(const uint32_t*)(Kc + n * KS + c0);
                    uint32_t b1 = *(const uint32_t*)(Kc + n * KS + c0 + 8);
                    mma16816(acc[j], a0, a1, a2, a3, b0, b1);
                }
            }

            // wait for Ps[p] to be free (producer finished attn write of tile kt-2)
            if (kt >= 2) bar_sync(B_PSFREE(p), THREADS);

            #pragma unroll
            for (int j = 0; j < 4; ++j) {
                const int col = (nh * 4 + j) * 8 + t * 2;
                float2 p01, p23;
                p01.x = __expf(acc[j][0] * SCALE) * inv0;
                p01.y = __expf(acc[j][1] * SCALE) * inv0;
                p23.x = __expf(acc[j][2] * SCALE) * inv1;
                p23.y = __expf(acc[j][3] * SCALE) * inv1;
                *(float2*)(Psp + (m0 + g    ) * PSS + col) = p01;
                *(float2*)(Psp + (m0 + g + 8) * PSS + col) = p23;
            }
            bar_arrive(B_PSFULL(p), THREADS);
            bar_sync(B_CONS, NCONS);   // all consumer Ps writes visible to consumers

            // P @ V
            #pragma unroll
            for (int kb2 = 0; kb2 < 4; ++kb2) {
                const int s0 = kb2 * 16;
                const int c0 = s0 + t * 2;
                uint32_t A0, A1, A2, A3;
                {
                    float2 f;
                    f = *(const float2*)(Psp + (mw + g    ) * PSS + c0);     A0 = pack_f2(f.x, f.y);
                    f = *(const float2*)(Psp + (mw + g + 8) * PSS + c0);     A1 = pack_f2(f.x, f.y);
                    f = *(const float2*)(Psp + (mw + g    ) * PSS + c0 + 8); A2 = pack_f2(f.x, f.y);
                    f = *(const float2*)(Psp + (mw + g + 8) * PSS + c0 + 8); A3 = pack_f2(f.x, f.y);
                }
                #pragma unroll
                for (int nb = 0; nb < 8; ++nb) {
                    const int d0 = nwc + nb * 8;
                    uint32_t b0, b1;
                    ldmx2t(b0, b1, Vc + (s0 + lr) * VHS + d0);
                    mma16816(cacc[nb], A0, A1, A2, A3, b0, b1);
                }
            }
            bar_arrive(B_KVFREE(p), THREADS);
        }

        // ---- write context ----
        float* cbase = ctx + ((size_t)(b * SEQ + q0)) * DIM;
        #pragma unroll
        for (int nb = 0; nb < 8; ++nb) {
            const int cc = nwc + nb * 8 + t * 2;
            float2 lo; lo.x = cacc[nb][0]; lo.y = cacc[nb][1];
            float2 hi; hi.x = cacc[nb][2]; hi.y = cacc[nb][3];
            *(float2*)(cbase + (size_t)(mw + g    ) * DIM + cc) = lo;
            *(float2*)(cbase + (size_t)(mw + g + 8) * DIM + cc) = hi;
        }
    }
}

extern "C" void kernel_launch(void* const* d_in, const int* in_sizes, int n_in,
                              void* d_out, int out_size)
{
    const float* q = (const float*)d_in[0];
    const float* k = (const float*)d_in[1];
    const float* v = (const float*)d_in[2];
    float* out  = (float*)d_out;
    float* ctx  = out;                                 // [16,2048,128]
    float* attn = out + (size_t)BATCH * SEQ * DIM;     // [16,2048,2048]

    cudaFuncSetAttribute(attn_kernel, cudaFuncAttributeMaxDynamicSharedMemorySize, SMEM_BYTES);
    dim3 grid(SEQ / TQ, BATCH);
    attn_kernel<<<grid, THREADS, SMEM_BYTES>>>(q, k, v, ctx, attn);
}

// round 8
// speedup vs baseline: 1.8407x; 1.8407x over previous
#include <cuda_runtime.h>
#include <cuda_fp16.h>
#include <cstdint>

#define BATCH 16
#define SEQ   2048
#define DIM   128
#define TQ    128
#define TK    64
#define THREADS 512
#define NTILE (SEQ/TK)
#define SCALE 0.08838834764831845f   // 1/sqrt(128)

// smem strides (elements)
#define QS  136   // halfs per Q row (272B, 16B aligned rows)
#define KS  136
#define VHS 136
#define PSS 68    // floats per P row (272B)

// smem layout (bytes)
#define OFF_Q  0
#define SZ_Q   (TQ*QS*2)
#define OFF_K  (OFF_Q + SZ_Q)
#define SZ_KB  (TK*KS*2)
#define OFF_V  (OFF_K + 2*SZ_KB)
#define SZ_VB  (TK*VHS*2)
#define OFF_P  (OFF_V + 2*SZ_VB)
#define SZ_P   (TQ*PSS*4)
#define OFF_R  (OFF_P + SZ_P)
#define OFF_SK (OFF_R + 512)
#define OFF_SV (OFF_SK + TK*DIM*4)
#define SMEM_BYTES (OFF_SV + TK*DIM*4)   // 205312

__device__ __forceinline__ void mma16816(float* c,
    uint32_t a0, uint32_t a1, uint32_t a2, uint32_t a3,
    uint32_t b0, uint32_t b1)
{
    asm volatile(
        "mma.sync.aligned.m16n8k16.row.col.f32.f16.f16.f32 "
        "{%0,%1,%2,%3}, {%4,%5,%6,%7}, {%8,%9}, {%0,%1,%2,%3};\n"
        : "+f"(c[0]), "+f"(c[1]), "+f"(c[2]), "+f"(c[3])
        : "r"(a0), "r"(a1), "r"(a2), "r"(a3), "r"(b0), "r"(b1));
}

__device__ __forceinline__ void ldmx4(uint32_t* r, const __half* p) {
    uint32_t s = (uint32_t)__cvta_generic_to_shared(p);
    asm volatile("ldmatrix.sync.aligned.m8n8.x4.shared.b16 {%0,%1,%2,%3}, [%4];"
        : "=r"(r[0]), "=r"(r[1]), "=r"(r[2]), "=r"(r[3]) : "r"(s));
}
__device__ __forceinline__ void ldmx4t(uint32_t* r, const __half* p) {
    uint32_t s = (uint32_t)__cvta_generic_to_shared(p);
    asm volatile("ldmatrix.sync.aligned.m8n8.x4.trans.shared.b16 {%0,%1,%2,%3}, [%4];"
        : "=r"(r[0]), "=r"(r[1]), "=r"(r[2]), "=r"(r[3]) : "r"(s));
}

__device__ __forceinline__ void cp16(void* smem_dst, const void* gptr) {
    uint32_t s = (uint32_t)__cvta_generic_to_shared(smem_dst);
    asm volatile("cp.async.cg.shared.global [%0], [%1], 16;" :: "r"(s), "l"(gptr));
}
#define CP_COMMIT() asm volatile("cp.async.commit_group;")
#define CP_WAIT0()  asm volatile("cp.async.wait_group 0;" ::: "memory")

__device__ __forceinline__ uint32_t pack_f2(float x, float y) {
    __half2 h = __floats2half2_rn(x, y);
    return *reinterpret_cast<uint32_t*>(&h);
}

__device__ __forceinline__ void issue_tile(char* stage, const float* g, int tid) {
    #pragma unroll
    for (int j = 0; j < 4; ++j) {
        int i = tid + j * THREADS;
        cp16(stage + i * 16, g + i * 4);
    }
}

__device__ __forceinline__ void conv_tile(const float* stage, __half* dst, int rs, int tid) {
    #pragma unroll
    for (int j = 0; j < 4; ++j) {
        int i = tid + j * THREADS;
        float4 f = ((const float4*)stage)[i];
        int r = i >> 5, c4 = (i & 31) << 2;
        __half2 h0 = __floats2half2_rn(f.x, f.y);
        __half2 h1 = __floats2half2_rn(f.z, f.w);
        uint2 u; u.x = *(uint32_t*)&h0; u.y = *(uint32_t*)&h1;
        *(uint2*)(dst + r * rs + c4) = u;
    }
}

__global__ __launch_bounds__(THREADS, 1)
void attn_kernel(const float* __restrict__ q, const float* __restrict__ k,
                 const float* __restrict__ v, float* __restrict__ ctx,
                 float* __restrict__ attn)
{
    extern __shared__ char smem[];
    __half* Qh  = reinterpret_cast<__half*>(smem + OFF_Q);
    __half* Kt0 = reinterpret_cast<__half*>(smem + OFF_K);
    __half* Vh0 = reinterpret_cast<__half*>(smem + OFF_V);
    float*  Ps  = reinterpret_cast<float*>(smem + OFF_P);
    float*  RI  = reinterpret_cast<float*>(smem + OFF_R);
    float*  stK = reinterpret_cast<float*>(smem + OFF_SK);
    float*  stV = reinterpret_cast<float*>(smem + OFF_SV);

    const int b    = blockIdx.y;
    const int q0   = blockIdx.x * TQ;
    const int tid  = threadIdx.x;
    const int w    = tid >> 5;
    const int lane = tid & 31;
    const int g    = lane >> 2;
    const int t    = lane & 3;

    const int m0 = (w >> 1) * 16;   // QK row block
    const int nh = (w & 1);         // QK column half

    if (tid < TQ) RI[tid] = 0.f;

    // ---- Q tile load+convert ----
    const float* qbase = q + ((size_t)(b * SEQ + q0)) * DIM;
    for (int i = tid; i < TQ * (DIM / 4); i += THREADS) {
        int r = i >> 5, c4 = (i & 31) << 2;
        float4 f = *(const float4*)(qbase + r * DIM + c4);
        __half2 h0 = __floats2half2_rn(f.x, f.y);
        __half2 h1 = __floats2half2_rn(f.z, f.w);
        uint2 u; u.x = *(uint32_t*)&h0; u.y = *(uint32_t*)&h1;
        *(uint2*)(Qh + r * QS + c4) = u;
    }
    __syncthreads();

    // ---- hoist Q fragments into registers (reused for all 64 tile passes) ----
    uint32_t qa[8][4];
    {
        const __half* qbaseS = Qh + (m0 + (lane & 15)) * QS + ((lane >> 4) << 3);
        #pragma unroll
        for (int kb2 = 0; kb2 < 8; ++kb2)
            ldmx4(qa[kb2], qbaseS + kb2 * 16);
    }

    const float* kbatch = k + ((size_t)b * SEQ) * DIM;
    const float* vbatch = v + ((size_t)b * SEQ) * DIM;

    // B-frag ldmatrix lane addressing (per kb2, two x4 loads cover j=0..3)
    const int bmat = lane >> 3;            // matrix index 0..3
    const int bj   = bmat >> 1;            // j offset within pair
    const int bkh  = (bmat & 1) << 3;      // k half offset (halfs)
    const int brow = lane & 7;

    // ================= SWEEP 1: row sums =================
    issue_tile((char*)stK, kbatch, tid); CP_COMMIT();
    CP_WAIT0();
    conv_tile(stK, Kt0, KS, tid);
    __syncthreads();
    issue_tile((char*)stK, kbatch + (size_t)TK * DIM, tid); CP_COMMIT();

    float rs0 = 0.f, rs1 = 0.f;

    for (int kt = 0; kt < NTILE; ++kt) {
        const __half* Kc = Kt0 + (kt & 1) * (SZ_KB / 2);
        float acc[4][4];
        #pragma unroll
        for (int j = 0; j < 4; ++j) { acc[j][0]=acc[j][1]=acc[j][2]=acc[j][3]=0.f; }

        #pragma unroll
        for (int kb2 = 0; kb2 < 8; ++kb2) {
            #pragma unroll
            for (int jp = 0; jp < 2; ++jp) {    // j pairs {0,1},{2,3}
                uint32_t bf[4];
                const int n = (nh * 4 + jp * 2 + bj) * 8 + brow;
                ldmx4(bf, Kc + n * KS + kb2 * 16 + bkh);
                mma16816(acc[jp*2  ], qa[kb2][0], qa[kb2][1], qa[kb2][2], qa[kb2][3], bf[0], bf[1]);
                mma16816(acc[jp*2+1], qa[kb2][0], qa[kb2][1], qa[kb2][2], qa[kb2][3], bf[2], bf[3]);
            }
        }
        #pragma unroll
        for (int j = 0; j < 4; ++j) {
            rs0 += __expf(acc[j][0] * SCALE) + __expf(acc[j][1] * SCALE);
            rs1 += __expf(acc[j][2] * SCALE) + __expf(acc[j][3] * SCALE);
        }

        if (kt < NTILE - 1) {
            CP_WAIT0();
            conv_tile(stK, Kt0 + ((kt + 1) & 1) * (SZ_KB / 2), KS, tid);
        }
        __syncthreads();
        if (kt < NTILE - 2) {
            issue_tile((char*)stK, kbatch + (size_t)(kt + 2) * TK * DIM, tid); CP_COMMIT();
        }
    }

    rs0 += __shfl_xor_sync(0xffffffffu, rs0, 1);
    rs0 += __shfl_xor_sync(0xffffffffu, rs0, 2);
    rs1 += __shfl_xor_sync(0xffffffffu, rs1, 1);
    rs1 += __shfl_xor_sync(0xffffffffu, rs1, 2);
    if (t == 0) {
        atomicAdd(&RI[m0 + g], rs0);
        atomicAdd(&RI[m0 + g + 8], rs1);
    }
    __syncthreads();
    if (tid < TQ) RI[tid] = 1.f / RI[tid];
    __syncthreads();

    const float inv0 = RI[m0 + g];
    const float inv1 = RI[m0 + g + 8];

    // ================= SWEEP 2 =================
    const int mw  = (w & 7) * 16;   // PV rows
    const int nwc = (w >> 3) * 64;  // PV cols
    float cacc[8][4];
    #pragma unroll
    for (int nb = 0; nb < 8; ++nb) { cacc[nb][0]=cacc[nb][1]=cacc[nb][2]=cacc[nb][3]=0.f; }

    // V trans-ldmatrix lane addressing: mat0/1 = s lo/hi at d0, mat2/3 = s lo/hi at d0+8
    const int vsh = (bmat & 1) << 3;       // s half
    const int vdh = (bmat >> 1) << 3;      // d half

    issue_tile((char*)stK, kbatch, tid);
    issue_tile((char*)stV, vbatch, tid);
    CP_COMMIT();
    CP_WAIT0();
    conv_tile(stK, Kt0, KS, tid);
    conv_tile(stV, Vh0, VHS, tid);
    __syncthreads();
    issue_tile((char*)stK, kbatch + (size_t)TK * DIM, tid);
    issue_tile((char*)stV, vbatch + (size_t)TK * DIM, tid);
    CP_COMMIT();

    float* attnbase = attn + ((size_t)(b * SEQ + q0)) * SEQ;

    for (int kt = 0; kt < NTILE; ++kt) {
        const __half* Kc = Kt0 + (kt & 1) * (SZ_KB / 2);
        const __half* Vc = Vh0 + (kt & 1) * (SZ_VB / 2);

        // --- QK recompute (identical arithmetic to sweep 1) ---
        float acc[4][4];
        #pragma unroll
        for (int j = 0; j < 4; ++j) { acc[j][0]=acc[j][1]=acc[j][2]=acc[j][3]=0.f; }
        #pragma unroll
        for (int kb2 = 0; kb2 < 8; ++kb2) {
            #pragma unroll
            for (int jp = 0; jp < 2; ++jp) {
                uint32_t bf[4];
                const int n = (nh * 4 + jp * 2 + bj) * 8 + brow;
                ldmx4(bf, Kc + n * KS + kb2 * 16 + bkh);
                mma16816(acc[jp*2  ], qa[kb2][0], qa[kb2][1], qa[kb2][2], qa[kb2][3], bf[0], bf[1]);
                mma16816(acc[jp*2+1], qa[kb2][0], qa[kb2][1], qa[kb2][2], qa[kb2][3], bf[2], bf[3]);
            }
        }
        // normalized probabilities -> Ps
        #pragma unroll
        for (int j = 0; j < 4; ++j) {
            const int col = (nh * 4 + j) * 8 + t * 2;
            float2 p01, p23;
            p01.x = __expf(acc[j][0] * SCALE) * inv0;
            p01.y = __expf(acc[j][1] * SCALE) * inv0;
            p23.x = __expf(acc[j][2] * SCALE) * inv1;
            p23.y = __expf(acc[j][3] * SCALE) * inv1;
            *(float2*)(Ps + (m0 + g    ) * PSS + col) = p01;
            *(float2*)(Ps + (m0 + g + 8) * PSS + col) = p23;
        }
        __syncthreads();

        // --- attention write, vectorized float4 (4 iters/thread) ---
        {
            float* ab = attnbase + kt * TK;
            #pragma unroll
            for (int it = 0; it < 4; ++it) {
                int i = tid + it * THREADS;          // 0..2047 float4 chunks
                int r = i >> 4, c4 = (i & 15) << 2;  // 16 float4 per 64-col row
                float4 f = *(const float4*)(Ps + r * PSS + c4);
                float* p = ab + (size_t)r * SEQ + c4;
                asm volatile("st.global.cs.v4.f32 [%0], {%1,%2,%3,%4};"
                    :: "l"(p), "f"(f.x), "f"(f.y), "f"(f.z), "f"(f.w));
            }
        }

        // --- P @ V ---
        #pragma unroll
        for (int kb2 = 0; kb2 < 4; ++kb2) {
            const int s0 = kb2 * 16;
            const int c0 = s0 + t * 2;
            uint32_t A0, A1, A2, A3;
            {
                float2 f;
                f = *(const float2*)(Ps + (mw + g    ) * PSS + c0);     A0 = pack_f2(f.x, f.y);
                f = *(const float2*)(Ps + (mw + g + 8) * PSS + c0);     A1 = pack_f2(f.x, f.y);
                f = *(const float2*)(Ps + (mw + g    ) * PSS + c0 + 8); A2 = pack_f2(f.x, f.y);
                f = *(const float2*)(Ps + (mw + g + 8) * PSS + c0 + 8); A3 = pack_f2(f.x, f.y);
            }
            #pragma unroll
            for (int nbp = 0; nbp < 4; ++nbp) {       // nb pairs
                const int d0 = nwc + nbp * 16;
                uint32_t bf[4];
                ldmx4t(bf, Vc + (s0 + vsh + brow) * VHS + d0 + vdh);
                mma16816(cacc[nbp*2  ], A0, A1, A2, A3, bf[0], bf[1]);
                mma16816(cacc[nbp*2+1], A0, A1, A2, A3, bf[2], bf[3]);
            }
        }

        if (kt < NTILE - 1) {
            CP_WAIT0();
            conv_tile(stK, Kt0 + ((kt + 1) & 1) * (SZ_KB / 2), KS, tid);
            conv_tile(stV, Vh0 + ((kt + 1) & 1) * (SZ_VB / 2), VHS, tid);
        }
        __syncthreads();
        if (kt < NTILE - 2) {
            issue_tile((char*)stK, kbatch + (size_t)(kt + 2) * TK * DIM, tid);
            issue_tile((char*)stV, vbatch + (size_t)(kt + 2) * TK * DIM, tid);
            CP_COMMIT();
        }
    }

    // ---- write context ----
    float* cbase = ctx + ((size_t)(b * SEQ + q0)) * DIM;
    #pragma unroll
    for (int nb = 0; nb < 8; ++nb) {
        const int cc = nwc + nb * 8 + t * 2;
        float2 lo; lo.x = cacc[nb][0]; lo.y = cacc[nb][1];
        float2 hi; hi.x = cacc[nb][2]; hi.y = cacc[nb][3];
        *(float2*)(cbase + (size_t)(mw + g    ) * DIM + cc) = lo;
        *(float2*)(cbase + (size_t)(mw + g + 8) * DIM + cc) = hi;
    }
}

extern "C" void kernel_launch(void* const* d_in, const int* in_sizes, int n_in,
                              void* d_out, int out_size)
{
    const float* q = (const float*)d_in[0];
    const float* k = (const float*)d_in[1];
    const float* v = (const float*)d_in[2];
    float* out  = (float*)d_out;
    float* ctx  = out;                                 // [16,2048,128]
    float* attn = out + (size_t)BATCH * SEQ * DIM;     // [16,2048,2048]

    cudaFuncSetAttribute(attn_kernel, cudaFuncAttributeMaxDynamicSharedMemorySize, SMEM_BYTES);
    dim3 grid(SEQ / TQ, BATCH);
    attn_kernel<<<grid, THREADS, SMEM_BYTES>>>(q, k, v, ctx, attn);
}